// round 14
// baseline (speedup 1.0000x reference)
#include <cuda_runtime.h>
#include <cuda_fp16.h>

#define T_TOKENS 8192
#define DM 1024
#define DH 4096
#define NE 8
#define CAP 1280   // int(1.25 * 8192 / 8)

// ---------------- static device scratch (no allocation allowed) ----------------
__device__ __half g_w1 [NE * (size_t)DM * DH];      // W1 fp16 [E][K=DM][N=DH]
__device__ __half g_w2 [NE * (size_t)DH * DM];      // W2 fp16 [E][K=DH][N=DM]
__device__ __half g_buf[NE * (size_t)CAP * DM];     // dispatched tokens fp16
__device__ __half g_h  [NE * (size_t)CAP * DH];     // hidden activations fp16
__device__ float g_part[2 * NE * (size_t)CAP * DM]; // GEMM2 split-K partials
__device__ float g_gates[T_TOKENS * NE];
__device__ float g_topval[T_TOKENS];
__device__ int   g_topidx[T_TOKENS];
__device__ int   g_rank [T_TOKENS];
__device__ int   g_used [NE];

// ---------------- PTX helpers (sm_80-level, valid under compute_103) ------
__device__ __forceinline__ unsigned smem_u32(const void* p) {
    unsigned a;
    asm("{ .reg .u64 t; cvta.to.shared.u64 t, %1; cvt.u32.u64 %0, t; }" : "=r"(a) : "l"(p));
    return a;
}
__device__ __forceinline__ void cp16(unsigned dst, const void* src) {
    asm volatile("cp.async.cg.shared.global [%0], [%1], 16;\n" :: "r"(dst), "l"(src));
}
#define CP_COMMIT() asm volatile("cp.async.commit_group;\n" ::: "memory")
#define CP_WAIT(n)  asm volatile("cp.async.wait_group %0;\n" :: "n"(n) : "memory")

__device__ __forceinline__ void ldsm4(unsigned* r, unsigned addr) {
    asm volatile("ldmatrix.sync.aligned.m8n8.x4.shared.b16 {%0,%1,%2,%3}, [%4];\n"
                 : "=r"(r[0]), "=r"(r[1]), "=r"(r[2]), "=r"(r[3]) : "r"(addr));
}
__device__ __forceinline__ void ldsm4t(unsigned* r, unsigned addr) {
    asm volatile("ldmatrix.sync.aligned.m8n8.x4.trans.shared.b16 {%0,%1,%2,%3}, [%4];\n"
                 : "=r"(r[0]), "=r"(r[1]), "=r"(r[2]), "=r"(r[3]) : "r"(addr));
}
__device__ __forceinline__ void mma_f16(float* d, const unsigned* a, const unsigned* b) {
    asm volatile(
        "mma.sync.aligned.m16n8k16.row.col.f32.f16.f16.f32 "
        "{%0,%1,%2,%3}, {%4,%5,%6,%7}, {%8,%9}, {%0,%1,%2,%3};\n"
        : "+f"(d[0]), "+f"(d[1]), "+f"(d[2]), "+f"(d[3])
        : "r"(a[0]), "r"(a[1]), "r"(a[2]), "r"(a[3]), "r"(b[0]), "r"(b[1]));
}
__device__ __forceinline__ unsigned packh2(__half a, __half b) {
    unsigned short ua = __half_as_ushort(a), ub = __half_as_ushort(b);
    return (unsigned)ua | ((unsigned)ub << 16);
}
__device__ __forceinline__ uint2 cvt4(float4 v) {
    return make_uint2(packh2(__float2half(v.x), __float2half(v.y)),
                      packh2(__float2half(v.z), __float2half(v.w)));
}

// ---------------- router: warp per token ----------------
__global__ __launch_bounds__(256) void router_kernel(
    const float* __restrict__ x,
    const float* __restrict__ rw,
    const float* __restrict__ rb)
{
    int warp = (blockIdx.x * blockDim.x + threadIdx.x) >> 5;
    int lane = threadIdx.x & 31;
    if (warp >= T_TOKENS) return;
    const float* xr = x + (size_t)warp * DM;

    float acc[NE];
    #pragma unroll
    for (int e = 0; e < NE; e++) acc[e] = 0.f;

    #pragma unroll 4
    for (int i = 0; i < DM / 32; i++) {
        int idx = i * 32 + lane;
        float xv = xr[idx];
        const float4* w4 = (const float4*)(rw + idx * NE);
        float4 w0 = w4[0], w1v = w4[1];
        acc[0] += xv * w0.x;  acc[1] += xv * w0.y;
        acc[2] += xv * w0.z;  acc[3] += xv * w0.w;
        acc[4] += xv * w1v.x; acc[5] += xv * w1v.y;
        acc[6] += xv * w1v.z; acc[7] += xv * w1v.w;
    }
    #pragma unroll
    for (int e = 0; e < NE; e++) {
        #pragma unroll
        for (int o = 16; o; o >>= 1)
            acc[e] += __shfl_xor_sync(0xffffffffu, acc[e], o);
    }
    if (lane == 0) {
        float lg[NE];
        float m = -1e30f;
        #pragma unroll
        for (int e = 0; e < NE; e++) { lg[e] = acc[e] + rb[e]; m = fmaxf(m, lg[e]); }
        float g[NE], s = 0.f;
        #pragma unroll
        for (int e = 0; e < NE; e++) { g[e] = __expf(lg[e] - m); s += g[e]; }
        float inv = 1.f / s;
        int   bi = 0;
        float bg = -1.f;
        #pragma unroll
        for (int e = 0; e < NE; e++) {
            g[e] *= inv;
            g_gates[(size_t)warp * NE + e] = g[e];
            if (g[e] > bg) { bg = g[e]; bi = e; }  // strict > => first-max, matches argmax
        }
        g_topidx[warp] = bi;
        g_topval[warp] = bg;
    }
}

// ---------------- scan: single block, shuffle-based per-expert prefix -------
// Token order: thread tid owns tokens [tid*8, tid*8+8); lanes/warps ascending
// => first-come order preserved. Only 2 __syncthreads total.
__global__ __launch_bounds__(1024) void scan_kernel(float* __restrict__ out, int y_elems)
{
    __shared__ int   swarp[32][NE];   // per-warp inclusive totals
    __shared__ int   swoff[32][NE];   // per-warp exclusive offsets
    __shared__ float simp [32][NE];   // per-warp importance sums

    int tid  = threadIdx.x;
    int lane = tid & 31;
    int wid  = tid >> 5;
    int base = tid * 8;

    int cnt[NE];
    int eloc[8];
    #pragma unroll
    for (int e = 0; e < NE; e++) cnt[e] = 0;
    #pragma unroll
    for (int j = 0; j < 8; j++) {
        int e = g_topidx[base + j];
        eloc[j] = e;
        cnt[e]++;
    }

    float imp[NE];
    #pragma unroll
    for (int e = 0; e < NE; e++) imp[e] = 0.f;
    #pragma unroll
    for (int j = 0; j < 8; j++) {
        const float* gp = &g_gates[(size_t)(base + j) * NE];
        #pragma unroll
        for (int e = 0; e < NE; e++) imp[e] += gp[e];
    }

    // warp-level: inclusive scan of cnt over lanes; xor-reduce of imp
    int inc[NE];
    #pragma unroll
    for (int e = 0; e < NE; e++) {
        inc[e] = cnt[e];
        #pragma unroll
        for (int o = 1; o < 32; o <<= 1) {
            int v = __shfl_up_sync(0xffffffffu, inc[e], o);
            if (lane >= o) inc[e] += v;
        }
        #pragma unroll
        for (int o = 16; o; o >>= 1)
            imp[e] += __shfl_xor_sync(0xffffffffu, imp[e], o);
    }
    if (lane == 31) {
        #pragma unroll
        for (int e = 0; e < NE; e++) swarp[wid][e] = inc[e];
    }
    if (lane == 0) {
        #pragma unroll
        for (int e = 0; e < NE; e++) simp[wid][e] = imp[e];
    }
    __syncthreads();

    // warp 0: scan the 32 warp totals, reduce importance, emit aux/used
    if (wid == 0) {
        float aux = 0.f;
        #pragma unroll
        for (int e = 0; e < NE; e++) {
            int t = swarp[lane][e];
            int v = t;
            #pragma unroll
            for (int o = 1; o < 32; o <<= 1) {
                int u = __shfl_up_sync(0xffffffffu, v, o);
                if (lane >= o) v += u;
            }
            swoff[lane][e] = v - t;                       // exclusive warp offset
            int tot = __shfl_sync(0xffffffffu, v, 31);    // grand total

            float fi = simp[lane][e];
            #pragma unroll
            for (int o = 16; o; o >>= 1)
                fi += __shfl_xor_sync(0xffffffffu, fi, o);

            if (lane == 0) {
                float load       = (float)tot / (float)T_TOKENS;
                float importance = fi / (float)T_TOKENS;
                aux += importance * load;
                int u = tot < CAP ? tot : CAP;
                g_used[e] = u;
                out[y_elems + 1 + e] = (float)u;
            }
        }
        if (lane == 0) out[y_elems] = aux * (float)NE * 0.01f;
    }
    __syncthreads();

    // per-token ranks
    int c2[NE];
    #pragma unroll
    for (int e = 0; e < NE; e++) c2[e] = swoff[wid][e] + inc[e] - cnt[e];
    #pragma unroll
    for (int j = 0; j < 8; j++) {
        int e = eloc[j];
        g_rank[base + j] = c2[e];
        c2[e]++;
    }
}

// ---------------- dispatch: block per token, write fp16; also convert W1 ----
__global__ __launch_bounds__(256) void dispatch_kernel(
    const float* __restrict__ x, const float* __restrict__ w1)
{
    // W1 fp32->fp16 conversion, spread over all 2,097,152 threads (4 float4 each).
    {
        size_t gtid = (size_t)blockIdx.x * 256 + threadIdx.x;
        const size_t stride = (size_t)T_TOKENS * 256;              // 2097152
        #pragma unroll
        for (int k = 0; k < 4; k++) {
            size_t i = gtid + (size_t)k * stride;                  // covers 8388608
            ((uint2*)g_w1)[i] = cvt4(((const float4*)w1)[i]);
        }
    }

    int t = blockIdx.x;
    int r = g_rank[t];
    if (r >= CAP) return;
    int e = g_topidx[t];
    float4 v = ((const float4*)(x + (size_t)t * DM))[threadIdx.x];
    size_t base = ((size_t)e * CAP + r) * (DM / 4) + threadIdx.x;
    ((uint2*)g_buf)[base] = make_uint2(
        packh2(__float2half(v.x), __float2half(v.y)),
        packh2(__float2half(v.z), __float2half(v.w)));
}

// ---------------- mma.sync grouped GEMM (pure fp16) ----------------
// Block tile 128(m) x 256(n), 256 threads, 8 warps (2x4), warp tile 64x64,
// k-staged 64, 4-stage cp.async pipeline, register-double-buffered fragments.
// GEMM1 grid.y has one extra row of CTAs that convert W2 fp32->fp16 and exit
// (overlaps the conversion with GEMM1 compute; GEMM2 launches strictly after).
#define A_PAD 144
#define B_PAD 528
#define OFF_B 18432
#define STAGE_STRIDE 52224
#define NSTAGE 4
#define FFN_SMEM (NSTAGE * STAGE_STRIDE)

template<int K, int NFULL>
__device__ __forceinline__ void load_stage(
    unsigned sbase, const __half* A, const __half* B, int k0, int col0, int tid)
{
    #pragma unroll
    for (int l = 0; l < 4; l++) {   // A: 1024 chunks (128 rows x 8)
        int i   = tid + l * 256;
        int row = i >> 3, c = i & 7;
        cp16(sbase + row * A_PAD + c * 16, A + (size_t)row * K + k0 + c * 8);
    }
    #pragma unroll
    for (int l = 0; l < 8; l++) {   // B: 2048 chunks (64 k-rows x 32)
        int i  = tid + l * 256;
        int kr = i >> 5, c = i & 31;
        cp16(sbase + OFF_B + kr * B_PAD + c * 16,
             B + (size_t)(k0 + kr) * NFULL + col0 + c * 8);
    }
    CP_COMMIT();
}

template<int K, int NFULL, bool RELU, bool FIRST, int KSPLIT>
__global__ __launch_bounds__(256, 1) void ffn_mma(
    const float* __restrict__ bias_g, const float* __restrict__ w2raw)
{
    constexpr int KPER = K / KSPLIT;
    constexpr int S = KPER / 64;

    extern __shared__ __align__(128) char smem[];
    int tid  = threadIdx.x;

    // Converter CTAs (GEMM1 only): blockIdx.y == CAP/128 -> convert a W2 slice.
    if (FIRST && blockIdx.y == CAP / 128) {
        int cid = blockIdx.z * gridDim.x + blockIdx.x;           // 0..127
        const size_t per = ((size_t)NE * DM * DH / 4) / 128;     // 65536 float4s
        size_t start = (size_t)cid * per;
        for (size_t i = start + tid; i < start + per; i += 256)
            ((uint2*)g_w2)[i] = cvt4(((const float4*)w2raw)[i]);
        return;
    }

    const int e     = blockIdx.z / KSPLIT;
    const int split = blockIdx.z % KSPLIT;
    const int row0  = blockIdx.y * 128;
    if (row0 >= g_used[e]) return;
    const int col0 = blockIdx.x * 256;

    const __half* A = (FIRST ? g_buf : g_h)
                      + ((size_t)e * CAP + row0) * K + (size_t)split * KPER;
    const __half* B = (FIRST ? g_w1 : g_w2)
                      + (size_t)e * K * NFULL + (size_t)split * KPER * NFULL;

    unsigned sb  = smem_u32(smem);
    int lane = tid & 31;
    int wid  = tid >> 5;
    int wm = (wid & 1) * 64;    // 2 warps along m
    int wn = (wid >> 1) * 64;   // 4 warps along n

    float acc[4][8][4];
    #pragma unroll
    for (int t = 0; t < 4; t++)
        #pragma unroll
        for (int n = 0; n < 8; n++)
            #pragma unroll
            for (int j = 0; j < 4; j++) acc[t][n][j] = 0.f;

    // ldmatrix lane address components
    unsigned a_row  = wm + (lane & 15);
    unsigned a_koff = (lane >> 4) * 16;     // byte offset (k half of 16-k chunk)
    unsigned b_krow = lane & 15;
    unsigned b_ncol = wn + ((lane & 16) ? 8 : 0);

    // double-buffered fragments
    unsigned ah[2][4][4], bh[2][8][2];

    auto ldfrag = [&](unsigned ab, int kk, int buf) {
        #pragma unroll
        for (int t = 0; t < 4; t++)
            ldsm4(ah[buf][t], ab + (a_row + t * 16) * A_PAD + kk * 32 + a_koff);
        #pragma unroll
        for (int h = 0; h < 4; h++) {
            unsigned r[4];
            ldsm4t(r, ab + OFF_B + (kk * 16 + b_krow) * B_PAD + (b_ncol + h * 16) * 2);
            bh[buf][h * 2][0] = r[0]; bh[buf][h * 2][1] = r[1];
            bh[buf][h * 2 + 1][0] = r[2]; bh[buf][h * 2 + 1][1] = r[3];
        }
    };

    // prologue: stages 0,1,2 in flight
    load_stage<K, NFULL>(sb, A, B, 0, col0, tid);
    load_stage<K, NFULL>(sb + STAGE_STRIDE, A, B, 64, col0, tid);
    load_stage<K, NFULL>(sb + 2 * STAGE_STRIDE, A, B, 128, col0, tid);

    #pragma unroll 1
    for (int s = 0; s < S; s++) {
        CP_WAIT(2);
        __syncthreads();
        if (s + 3 < S)
            load_stage<K, NFULL>(sb + ((s + 3) % NSTAGE) * STAGE_STRIDE, A, B,
                                 (s + 3) * 64, col0, tid);
        else
            CP_COMMIT();     // empty group keeps wait accounting uniform

        unsigned ab = sb + (s % NSTAGE) * STAGE_STRIDE;
        ldfrag(ab, 0, 0);
        #pragma unroll
        for (int kk = 0; kk < 4; kk++) {
            int cur = kk & 1;
            if (kk < 3) ldfrag(ab, kk + 1, cur ^ 1);
            #pragma unroll
            for (int t = 0; t < 4; t++)
                #pragma unroll
                for (int n = 0; n < 8; n++)
                    mma_f16(acc[t][n], ah[cur][t], bh[cur][n]);
        }
    }

    // epilogue
    int r0l   = lane >> 2;
    int cpair = (lane & 3) * 2;
    if (FIRST) {
        const float* bias = bias_g + (size_t)e * NFULL + col0;
        #pragma unroll
        for (int t = 0; t < 4; t++) {
            #pragma unroll
            for (int n = 0; n < 8; n++) {
                int col = wn + n * 8 + cpair;
                float b0 = __ldg(bias + col), b1 = __ldg(bias + col + 1);
                int rowA = row0 + wm + t * 16 + r0l;
                #pragma unroll
                for (int half = 0; half < 2; half++) {
                    int rg = rowA + half * 8;
                    float v0 = fmaxf(acc[t][n][half * 2]     + b0, 0.f);
                    float v1 = fmaxf(acc[t][n][half * 2 + 1] + b1, 0.f);
                    size_t idx = ((size_t)e * CAP + rg) * NFULL + col0 + col;
                    ((unsigned*)g_h)[idx >> 1] = packh2(__float2half(v0), __float2half(v1));
                }
            }
        }
    } else {
        float* part = g_part + (size_t)split * NE * (size_t)CAP * DM;
        #pragma unroll
        for (int t = 0; t < 4; t++) {
            #pragma unroll
            for (int n = 0; n < 8; n++) {
                int col = wn + n * 8 + cpair;
                int rowA = row0 + wm + t * 16 + r0l;
                #pragma unroll
                for (int half = 0; half < 2; half++) {
                    int rg = rowA + half * 8;
                    size_t idx = ((size_t)e * CAP + rg) * NFULL + col0 + col;
                    *(float2*)(part + idx) =
                        make_float2(acc[t][n][half * 2], acc[t][n][half * 2 + 1]);
                }
            }
        }
    }
}

// ---------------- combine: sum split-K partials + bias, scale by gate ------
__global__ __launch_bounds__(256) void combine_kernel(
    float* __restrict__ out, const float* __restrict__ b2)
{
    int t = blockIdx.x;
    int r = g_rank[t];
    float4* dst = (float4*)(out + (size_t)t * DM);
    if (r < CAP) {
        int   e = g_topidx[t];
        float v = g_topval[t];
        size_t idx = ((size_t)e * CAP + r) * (DM / 4) + threadIdx.x;
        float4 p0 = ((const float4*)g_part)[idx];
        float4 p1 = ((const float4*)g_part)[idx + (size_t)NE * CAP * DM / 4];
        float4 b  = ((const float4*)(b2 + (size_t)e * DM))[threadIdx.x];
        float4 s;
        s.x = (p0.x + p1.x + b.x) * v;
        s.y = (p0.y + p1.y + b.y) * v;
        s.z = (p0.z + p1.z + b.z) * v;
        s.w = (p0.w + p1.w + b.w) * v;
        dst[threadIdx.x] = s;
    } else {
        dst[threadIdx.x] = make_float4(0.f, 0.f, 0.f, 0.f);
    }
}

extern "C" void kernel_launch(void* const* d_in, const int* in_sizes, int n_in,
                              void* d_out, int out_size)
{
    const float* x  = (const float*)d_in[0];
    const float* rw = (const float*)d_in[1];
    const float* rb = (const float*)d_in[2];
    const float* w1 = (const float*)d_in[3];
    const float* b1 = (const float*)d_in[4];
    const float* w2 = (const float*)d_in[5];
    const float* b2 = (const float*)d_in[6];
    float* out = (float*)d_out;

    int y_elems = in_sizes[0];

    cudaFuncSetAttribute(ffn_mma<DM, DH, true,  true,  1>,
                         cudaFuncAttributeMaxDynamicSharedMemorySize, FFN_SMEM);
    cudaFuncSetAttribute(ffn_mma<DH, DM, false, false, 2>,
                         cudaFuncAttributeMaxDynamicSharedMemorySize, FFN_SMEM);

    router_kernel<<<T_TOKENS / 8, 256>>>(x, rw, rb);
    scan_kernel<<<1, 1024>>>(out, y_elems);
    dispatch_kernel<<<T_TOKENS, 256>>>(x, w1);

    // GEMM1: grid.y = CAP/128 + 1; the extra row converts W2 (overlapped).
    ffn_mma<DM, DH, true,  true,  1>
        <<<dim3(DH / 256, CAP / 128 + 1, NE),     256, FFN_SMEM>>>(b1, w2);
    ffn_mma<DH, DM, false, false, 2>
        <<<dim3(DM / 256, CAP / 128, NE * 2),     256, FFN_SMEM>>>(b2, nullptr);

    combine_kernel<<<T_TOKENS, 256>>>(out, b2);
}

// round 15
// speedup vs baseline: 1.0272x; 1.0272x over previous
#include <cuda_runtime.h>
#include <cuda_fp16.h>

#define T_TOKENS 8192
#define DM 1024
#define DH 4096
#define NE 8
#define CAP 1280   // int(1.25 * 8192 / 8)

// ---------------- static device scratch (no allocation allowed) ----------------
__device__ __half g_w1 [NE * (size_t)DM * DH];      // W1 fp16 [E][K=DM][N=DH]
__device__ __half g_w2 [NE * (size_t)DH * DM];      // W2 fp16 [E][K=DH][N=DM]
__device__ __half g_buf[NE * (size_t)CAP * DM];     // dispatched tokens fp16
__device__ __half g_h  [NE * (size_t)CAP * DH];     // hidden activations fp16
__device__ float g_part[2 * NE * (size_t)CAP * DM]; // GEMM2 split-K partials
__device__ float g_gates[T_TOKENS * NE];
__device__ float g_topval[T_TOKENS];
__device__ int   g_topidx[T_TOKENS];
__device__ int   g_rank [T_TOKENS];
__device__ int   g_used [NE];

// ---------------- PTX helpers (sm_80-level, valid under compute_103) ------
__device__ __forceinline__ unsigned smem_u32(const void* p) {
    unsigned a;
    asm("{ .reg .u64 t; cvta.to.shared.u64 t, %1; cvt.u32.u64 %0, t; }" : "=r"(a) : "l"(p));
    return a;
}
__device__ __forceinline__ void cp16(unsigned dst, const void* src) {
    asm volatile("cp.async.cg.shared.global [%0], [%1], 16;\n" :: "r"(dst), "l"(src));
}
#define CP_COMMIT() asm volatile("cp.async.commit_group;\n" ::: "memory")
#define CP_WAIT(n)  asm volatile("cp.async.wait_group %0;\n" :: "n"(n) : "memory")

__device__ __forceinline__ void ldsm4(unsigned* r, unsigned addr) {
    asm volatile("ldmatrix.sync.aligned.m8n8.x4.shared.b16 {%0,%1,%2,%3}, [%4];\n"
                 : "=r"(r[0]), "=r"(r[1]), "=r"(r[2]), "=r"(r[3]) : "r"(addr));
}
__device__ __forceinline__ void ldsm4t(unsigned* r, unsigned addr) {
    asm volatile("ldmatrix.sync.aligned.m8n8.x4.trans.shared.b16 {%0,%1,%2,%3}, [%4];\n"
                 : "=r"(r[0]), "=r"(r[1]), "=r"(r[2]), "=r"(r[3]) : "r"(addr));
}
__device__ __forceinline__ void mma_f16(float* d, const unsigned* a, const unsigned* b) {
    asm volatile(
        "mma.sync.aligned.m16n8k16.row.col.f32.f16.f16.f32 "
        "{%0,%1,%2,%3}, {%4,%5,%6,%7}, {%8,%9}, {%0,%1,%2,%3};\n"
        : "+f"(d[0]), "+f"(d[1]), "+f"(d[2]), "+f"(d[3])
        : "r"(a[0]), "r"(a[1]), "r"(a[2]), "r"(a[3]), "r"(b[0]), "r"(b[1]));
}
__device__ __forceinline__ unsigned packh2(__half a, __half b) {
    unsigned short ua = __half_as_ushort(a), ub = __half_as_ushort(b);
    return (unsigned)ua | ((unsigned)ub << 16);
}

// ---------------- router: warp per token ----------------
__global__ __launch_bounds__(256) void router_kernel(
    const float* __restrict__ x,
    const float* __restrict__ rw,
    const float* __restrict__ rb)
{
    int warp = (blockIdx.x * blockDim.x + threadIdx.x) >> 5;
    int lane = threadIdx.x & 31;
    if (warp >= T_TOKENS) return;
    const float* xr = x + (size_t)warp * DM;

    float acc[NE];
    #pragma unroll
    for (int e = 0; e < NE; e++) acc[e] = 0.f;

    #pragma unroll 4
    for (int i = 0; i < DM / 32; i++) {
        int idx = i * 32 + lane;
        float xv = xr[idx];
        const float4* w4 = (const float4*)(rw + idx * NE);
        float4 w0 = w4[0], w1v = w4[1];
        acc[0] += xv * w0.x;  acc[1] += xv * w0.y;
        acc[2] += xv * w0.z;  acc[3] += xv * w0.w;
        acc[4] += xv * w1v.x; acc[5] += xv * w1v.y;
        acc[6] += xv * w1v.z; acc[7] += xv * w1v.w;
    }
    #pragma unroll
    for (int e = 0; e < NE; e++) {
        #pragma unroll
        for (int o = 16; o; o >>= 1)
            acc[e] += __shfl_xor_sync(0xffffffffu, acc[e], o);
    }
    if (lane == 0) {
        float lg[NE];
        float m = -1e30f;
        #pragma unroll
        for (int e = 0; e < NE; e++) { lg[e] = acc[e] + rb[e]; m = fmaxf(m, lg[e]); }
        float g[NE], s = 0.f;
        #pragma unroll
        for (int e = 0; e < NE; e++) { g[e] = __expf(lg[e] - m); s += g[e]; }
        float inv = 1.f / s;
        int   bi = 0;
        float bg = -1.f;
        #pragma unroll
        for (int e = 0; e < NE; e++) {
            g[e] *= inv;
            g_gates[(size_t)warp * NE + e] = g[e];
            if (g[e] > bg) { bg = g[e]; bi = e; }  // strict > => first-max, matches argmax
        }
        g_topidx[warp] = bi;
        g_topval[warp] = bg;
    }
}

// ---------------- scan: single block, shuffle-based per-expert prefix -------
// Token order: thread tid owns tokens [tid*8, tid*8+8); lanes/warps ascending
// => first-come order preserved. Only 2 __syncthreads total.
__global__ __launch_bounds__(1024) void scan_kernel(float* __restrict__ out, int y_elems)
{
    __shared__ int   swarp[32][NE];   // per-warp inclusive totals
    __shared__ int   swoff[32][NE];   // per-warp exclusive offsets
    __shared__ float simp [32][NE];   // per-warp importance sums

    int tid  = threadIdx.x;
    int lane = tid & 31;
    int wid  = tid >> 5;
    int base = tid * 8;

    int cnt[NE];
    int eloc[8];
    #pragma unroll
    for (int e = 0; e < NE; e++) cnt[e] = 0;
    #pragma unroll
    for (int j = 0; j < 8; j++) {
        int e = g_topidx[base + j];
        eloc[j] = e;
        cnt[e]++;
    }

    float imp[NE];
    #pragma unroll
    for (int e = 0; e < NE; e++) imp[e] = 0.f;
    #pragma unroll
    for (int j = 0; j < 8; j++) {
        const float* gp = &g_gates[(size_t)(base + j) * NE];
        #pragma unroll
        for (int e = 0; e < NE; e++) imp[e] += gp[e];
    }

    // warp-level: inclusive scan of cnt over lanes; xor-reduce of imp
    int inc[NE];
    #pragma unroll
    for (int e = 0; e < NE; e++) {
        inc[e] = cnt[e];
        #pragma unroll
        for (int o = 1; o < 32; o <<= 1) {
            int v = __shfl_up_sync(0xffffffffu, inc[e], o);
            if (lane >= o) inc[e] += v;
        }
        #pragma unroll
        for (int o = 16; o; o >>= 1)
            imp[e] += __shfl_xor_sync(0xffffffffu, imp[e], o);
    }
    if (lane == 31) {
        #pragma unroll
        for (int e = 0; e < NE; e++) swarp[wid][e] = inc[e];
    }
    if (lane == 0) {
        #pragma unroll
        for (int e = 0; e < NE; e++) simp[wid][e] = imp[e];
    }
    __syncthreads();

    // warp 0: scan the 32 warp totals, reduce importance, emit aux/used
    if (wid == 0) {
        float aux = 0.f;
        #pragma unroll
        for (int e = 0; e < NE; e++) {
            int t = swarp[lane][e];
            int v = t;
            #pragma unroll
            for (int o = 1; o < 32; o <<= 1) {
                int u = __shfl_up_sync(0xffffffffu, v, o);
                if (lane >= o) v += u;
            }
            swoff[lane][e] = v - t;                       // exclusive warp offset
            int tot = __shfl_sync(0xffffffffu, v, 31);    // grand total

            float fi = simp[lane][e];
            #pragma unroll
            for (int o = 16; o; o >>= 1)
                fi += __shfl_xor_sync(0xffffffffu, fi, o);

            if (lane == 0) {
                float load       = (float)tot / (float)T_TOKENS;
                float importance = fi / (float)T_TOKENS;
                aux += importance * load;
                int u = tot < CAP ? tot : CAP;
                g_used[e] = u;
                out[y_elems + 1 + e] = (float)u;
            }
        }
        if (lane == 0) out[y_elems] = aux * (float)NE * 0.01f;
    }
    __syncthreads();

    // per-token ranks
    int c2[NE];
    #pragma unroll
    for (int e = 0; e < NE; e++) c2[e] = swoff[wid][e] + inc[e] - cnt[e];
    #pragma unroll
    for (int j = 0; j < 8; j++) {
        int e = eloc[j];
        g_rank[base + j] = c2[e];
        c2[e]++;
    }
}

// ---------------- dispatch: block per token, write fp16 ----------------
__global__ __launch_bounds__(256) void dispatch_kernel(const float* __restrict__ x)
{
    int t = blockIdx.x;
    int r = g_rank[t];
    if (r >= CAP) return;
    int e = g_topidx[t];
    float4 v = ((const float4*)(x + (size_t)t * DM))[threadIdx.x];
    size_t base = ((size_t)e * CAP + r) * (DM / 4) + threadIdx.x;
    ((uint2*)g_buf)[base] = make_uint2(
        packh2(__float2half(v.x), __float2half(v.y)),
        packh2(__float2half(v.z), __float2half(v.w)));
}

// ---------------- weight fp32 -> fp16 convert (both W1, W2; layout preserved) ---
__global__ __launch_bounds__(256) void convert_w(
    const float* __restrict__ w1, const float* __restrict__ w2)
{
    size_t n4 = (size_t)NE * DM * DH / 4;
    for (size_t i = (size_t)blockIdx.x * blockDim.x + threadIdx.x; i < n4;
         i += (size_t)gridDim.x * blockDim.x) {
        float4 a = ((const float4*)w1)[i];
        ((uint2*)g_w1)[i] = make_uint2(packh2(__float2half(a.x), __float2half(a.y)),
                                       packh2(__float2half(a.z), __float2half(a.w)));
        float4 b = ((const float4*)w2)[i];
        ((uint2*)g_w2)[i] = make_uint2(packh2(__float2half(b.x), __float2half(b.y)),
                                       packh2(__float2half(b.z), __float2half(b.w)));
    }
}

// ---------------- mma.sync grouped GEMM (pure fp16) ----------------
// Block tile 128(m) x 256(n), 256 threads, 8 warps (2x4), warp tile 64x64,
// k-staged 64, 4-stage cp.async pipeline, register-double-buffered fragments.
#define A_PAD 144
#define B_PAD 528
#define OFF_B 18432
#define STAGE_STRIDE 52224
#define NSTAGE 4
#define FFN_SMEM (NSTAGE * STAGE_STRIDE)

template<int K, int NFULL>
__device__ __forceinline__ void load_stage(
    unsigned sbase, const __half* A, const __half* B, int k0, int col0, int tid)
{
    #pragma unroll
    for (int l = 0; l < 4; l++) {   // A: 1024 chunks (128 rows x 8)
        int i   = tid + l * 256;
        int row = i >> 3, c = i & 7;
        cp16(sbase + row * A_PAD + c * 16, A + (size_t)row * K + k0 + c * 8);
    }
    #pragma unroll
    for (int l = 0; l < 8; l++) {   // B: 2048 chunks (64 k-rows x 32)
        int i  = tid + l * 256;
        int kr = i >> 5, c = i & 31;
        cp16(sbase + OFF_B + kr * B_PAD + c * 16,
             B + (size_t)(k0 + kr) * NFULL + col0 + c * 8);
    }
    CP_COMMIT();
}

template<int K, int NFULL, bool RELU, bool FIRST, int KSPLIT>
__global__ __launch_bounds__(256, 1) void ffn_mma(const float* __restrict__ bias_g)
{
    constexpr int KPER = K / KSPLIT;
    constexpr int S = KPER / 64;

    extern __shared__ __align__(128) char smem[];
    const int e     = blockIdx.z / KSPLIT;
    const int split = blockIdx.z % KSPLIT;
    const int row0  = blockIdx.y * 128;
    if (row0 >= g_used[e]) return;
    const int col0 = blockIdx.x * 256;

    const __half* A = (FIRST ? g_buf : g_h)
                      + ((size_t)e * CAP + row0) * K + (size_t)split * KPER;
    const __half* B = (FIRST ? g_w1 : g_w2)
                      + (size_t)e * K * NFULL + (size_t)split * KPER * NFULL;

    unsigned sb  = smem_u32(smem);
    int tid  = threadIdx.x;
    int lane = tid & 31;
    int wid  = tid >> 5;
    int wm = (wid & 1) * 64;    // 2 warps along m
    int wn = (wid >> 1) * 64;   // 4 warps along n

    float acc[4][8][4];
    #pragma unroll
    for (int t = 0; t < 4; t++)
        #pragma unroll
        for (int n = 0; n < 8; n++)
            #pragma unroll
            for (int j = 0; j < 4; j++) acc[t][n][j] = 0.f;

    // ldmatrix lane address components
    unsigned a_row  = wm + (lane & 15);
    unsigned a_koff = (lane >> 4) * 16;     // byte offset (k half of 16-k chunk)
    unsigned b_krow = lane & 15;
    unsigned b_ncol = wn + ((lane & 16) ? 8 : 0);

    // double-buffered fragments
    unsigned ah[2][4][4], bh[2][8][2];

    auto ldfrag = [&](unsigned ab, int kk, int buf) {
        #pragma unroll
        for (int t = 0; t < 4; t++)
            ldsm4(ah[buf][t], ab + (a_row + t * 16) * A_PAD + kk * 32 + a_koff);
        #pragma unroll
        for (int h = 0; h < 4; h++) {
            unsigned r[4];
            ldsm4t(r, ab + OFF_B + (kk * 16 + b_krow) * B_PAD + (b_ncol + h * 16) * 2);
            bh[buf][h * 2][0] = r[0]; bh[buf][h * 2][1] = r[1];
            bh[buf][h * 2 + 1][0] = r[2]; bh[buf][h * 2 + 1][1] = r[3];
        }
    };

    // prologue: stages 0,1,2 in flight
    load_stage<K, NFULL>(sb, A, B, 0, col0, tid);
    load_stage<K, NFULL>(sb + STAGE_STRIDE, A, B, 64, col0, tid);
    load_stage<K, NFULL>(sb + 2 * STAGE_STRIDE, A, B, 128, col0, tid);

    #pragma unroll 1
    for (int s = 0; s < S; s++) {
        CP_WAIT(2);
        __syncthreads();
        if (s + 3 < S)
            load_stage<K, NFULL>(sb + ((s + 3) % NSTAGE) * STAGE_STRIDE, A, B,
                                 (s + 3) * 64, col0, tid);
        else
            CP_COMMIT();     // empty group keeps wait accounting uniform

        unsigned ab = sb + (s % NSTAGE) * STAGE_STRIDE;
        ldfrag(ab, 0, 0);
        #pragma unroll
        for (int kk = 0; kk < 4; kk++) {
            int cur = kk & 1;
            if (kk < 3) ldfrag(ab, kk + 1, cur ^ 1);
            #pragma unroll
            for (int t = 0; t < 4; t++)
                #pragma unroll
                for (int n = 0; n < 8; n++)
                    mma_f16(acc[t][n], ah[cur][t], bh[cur][n]);
        }
    }

    // epilogue
    int r0l   = lane >> 2;
    int cpair = (lane & 3) * 2;
    if (FIRST) {
        const float* bias = bias_g + (size_t)e * NFULL + col0;
        #pragma unroll
        for (int t = 0; t < 4; t++) {
            #pragma unroll
            for (int n = 0; n < 8; n++) {
                int col = wn + n * 8 + cpair;
                float b0 = __ldg(bias + col), b1 = __ldg(bias + col + 1);
                int rowA = row0 + wm + t * 16 + r0l;
                #pragma unroll
                for (int half = 0; half < 2; half++) {
                    int rg = rowA + half * 8;
                    float v0 = fmaxf(acc[t][n][half * 2]     + b0, 0.f);
                    float v1 = fmaxf(acc[t][n][half * 2 + 1] + b1, 0.f);
                    size_t idx = ((size_t)e * CAP + rg) * NFULL + col0 + col;
                    ((unsigned*)g_h)[idx >> 1] = packh2(__float2half(v0), __float2half(v1));
                }
            }
        }
    } else {
        float* part = g_part + (size_t)split * NE * (size_t)CAP * DM;
        #pragma unroll
        for (int t = 0; t < 4; t++) {
            #pragma unroll
            for (int n = 0; n < 8; n++) {
                int col = wn + n * 8 + cpair;
                int rowA = row0 + wm + t * 16 + r0l;
                #pragma unroll
                for (int half = 0; half < 2; half++) {
                    int rg = rowA + half * 8;
                    size_t idx = ((size_t)e * CAP + rg) * NFULL + col0 + col;
                    *(float2*)(part + idx) =
                        make_float2(acc[t][n][half * 2], acc[t][n][half * 2 + 1]);
                }
            }
        }
    }
}

// ---------------- combine: sum split-K partials + bias, scale by gate ------
__global__ __launch_bounds__(256) void combine_kernel(
    float* __restrict__ out, const float* __restrict__ b2)
{
    int t = blockIdx.x;
    int r = g_rank[t];
    float4* dst = (float4*)(out + (size_t)t * DM);
    if (r < CAP) {
        int   e = g_topidx[t];
        float v = g_topval[t];
        size_t idx = ((size_t)e * CAP + r) * (DM / 4) + threadIdx.x;
        float4 p0 = ((const float4*)g_part)[idx];
        float4 p1 = ((const float4*)g_part)[idx + (size_t)NE * CAP * DM / 4];
        float4 b  = ((const float4*)(b2 + (size_t)e * DM))[threadIdx.x];
        float4 s;
        s.x = (p0.x + p1.x + b.x) * v;
        s.y = (p0.y + p1.y + b.y) * v;
        s.z = (p0.z + p1.z + b.z) * v;
        s.w = (p0.w + p1.w + b.w) * v;
        dst[threadIdx.x] = s;
    } else {
        dst[threadIdx.x] = make_float4(0.f, 0.f, 0.f, 0.f);
    }
}

extern "C" void kernel_launch(void* const* d_in, const int* in_sizes, int n_in,
                              void* d_out, int out_size)
{
    const float* x  = (const float*)d_in[0];
    const float* rw = (const float*)d_in[1];
    const float* rb = (const float*)d_in[2];
    const float* w1 = (const float*)d_in[3];
    const float* b1 = (const float*)d_in[4];
    const float* w2 = (const float*)d_in[5];
    const float* b2 = (const float*)d_in[6];
    float* out = (float*)d_out;

    int y_elems = in_sizes[0];

    cudaFuncSetAttribute(ffn_mma<DM, DH, true,  true,  1>,
                         cudaFuncAttributeMaxDynamicSharedMemorySize, FFN_SMEM);
    cudaFuncSetAttribute(ffn_mma<DH, DM, false, false, 2>,
                         cudaFuncAttributeMaxDynamicSharedMemorySize, FFN_SMEM);

    // Fork a side branch for weight conversion (independent of routing chain).
    cudaStream_t s2;
    cudaStreamCreateWithFlags(&s2, cudaStreamNonBlocking);
    cudaEvent_t evFork, evJoin;
    cudaEventCreateWithFlags(&evFork, cudaEventDisableTiming);
    cudaEventCreateWithFlags(&evJoin, cudaEventDisableTiming);

    cudaEventRecord(evFork, 0);
    cudaStreamWaitEvent(s2, evFork, 0);
    convert_w<<<4096, 256, 0, s2>>>(w1, w2);
    cudaEventRecord(evJoin, s2);

    // Main chain (capture/default stream), concurrent with convert_w.
    router_kernel<<<T_TOKENS / 8, 256>>>(x, rw, rb);
    scan_kernel<<<1, 1024>>>(out, y_elems);
    dispatch_kernel<<<T_TOKENS, 256>>>(x);

    // Join: GEMMs need converted weights.
    cudaStreamWaitEvent(0, evJoin, 0);

    ffn_mma<DM, DH, true,  true,  1><<<dim3(DH / 256, CAP / 128, NE),     256, FFN_SMEM>>>(b1);
    ffn_mma<DH, DM, false, false, 2><<<dim3(DM / 256, CAP / 128, NE * 2), 256, FFN_SMEM>>>(b2);

    combine_kernel<<<T_TOKENS, 256>>>(out, b2);

    cudaEventDestroy(evFork);
    cudaEventDestroy(evJoin);
    cudaStreamDestroy(s2);
}

// round 17
// speedup vs baseline: 1.0415x; 1.0139x over previous
#include <cuda_runtime.h>
#include <cuda_fp16.h>

#define T_TOKENS 8192
#define DM 1024
#define DH 4096
#define NE 8
#define CAP 1280   // int(1.25 * 8192 / 8)

// ---------------- static device scratch (no allocation allowed) ----------------
__device__ __half g_w1 [NE * (size_t)DM * DH];      // W1 fp16 [E][K=DM][N=DH]
__device__ __half g_w2 [NE * (size_t)DH * DM];      // W2 fp16 [E][K=DH][N=DM]
__device__ __half g_buf[NE * (size_t)CAP * DM];     // dispatched tokens fp16
__device__ __half g_h  [NE * (size_t)CAP * DH];     // hidden activations fp16
__device__ float g_part[2 * NE * (size_t)CAP * DM]; // GEMM2 split-K partials
__device__ float g_gates[T_TOKENS * NE];
__device__ float g_topval[T_TOKENS];
__device__ int   g_topidx[T_TOKENS];
__device__ int   g_rank [T_TOKENS];
__device__ int   g_used [NE];

// ---------------- PTX helpers (sm_80-level, valid under compute_103) ------
__device__ __forceinline__ unsigned smem_u32(const void* p) {
    unsigned a;
    asm("{ .reg .u64 t; cvta.to.shared.u64 t, %1; cvt.u32.u64 %0, t; }" : "=r"(a) : "l"(p));
    return a;
}
__device__ __forceinline__ void cp16(unsigned dst, const void* src) {
    asm volatile("cp.async.cg.shared.global [%0], [%1], 16;\n" :: "r"(dst), "l"(src));
}
#define CP_COMMIT() asm volatile("cp.async.commit_group;\n" ::: "memory")
#define CP_WAIT(n)  asm volatile("cp.async.wait_group %0;\n" :: "n"(n) : "memory")

__device__ __forceinline__ void ldsm4(unsigned* r, unsigned addr) {
    asm volatile("ldmatrix.sync.aligned.m8n8.x4.shared.b16 {%0,%1,%2,%3}, [%4];\n"
                 : "=r"(r[0]), "=r"(r[1]), "=r"(r[2]), "=r"(r[3]) : "r"(addr));
}
__device__ __forceinline__ void ldsm4t(unsigned* r, unsigned addr) {
    asm volatile("ldmatrix.sync.aligned.m8n8.x4.trans.shared.b16 {%0,%1,%2,%3}, [%4];\n"
                 : "=r"(r[0]), "=r"(r[1]), "=r"(r[2]), "=r"(r[3]) : "r"(addr));
}
__device__ __forceinline__ void mma_f16(float* d, const unsigned* a, const unsigned* b) {
    asm volatile(
        "mma.sync.aligned.m16n8k16.row.col.f32.f16.f16.f32 "
        "{%0,%1,%2,%3}, {%4,%5,%6,%7}, {%8,%9}, {%0,%1,%2,%3};\n"
        : "+f"(d[0]), "+f"(d[1]), "+f"(d[2]), "+f"(d[3])
        : "r"(a[0]), "r"(a[1]), "r"(a[2]), "r"(a[3]), "r"(b[0]), "r"(b[1]));
}
__device__ __forceinline__ unsigned packh2(__half a, __half b) {
    unsigned short ua = __half_as_ushort(a), ub = __half_as_ushort(b);
    return (unsigned)ua | ((unsigned)ub << 16);
}

// ---------------- router: warp per token ----------------
__global__ __launch_bounds__(256) void router_kernel(
    const float* __restrict__ x,
    const float* __restrict__ rw,
    const float* __restrict__ rb)
{
    int warp = (blockIdx.x * blockDim.x + threadIdx.x) >> 5;
    int lane = threadIdx.x & 31;
    if (warp >= T_TOKENS) return;
    const float* xr = x + (size_t)warp * DM;

    float acc[NE];
    #pragma unroll
    for (int e = 0; e < NE; e++) acc[e] = 0.f;

    #pragma unroll 4
    for (int i = 0; i < DM / 32; i++) {
        int idx = i * 32 + lane;
        float xv = xr[idx];
        const float4* w4 = (const float4*)(rw + idx * NE);
        float4 w0 = w4[0], w1v = w4[1];
        acc[0] += xv * w0.x;  acc[1] += xv * w0.y;
        acc[2] += xv * w0.z;  acc[3] += xv * w0.w;
        acc[4] += xv * w1v.x; acc[5] += xv * w1v.y;
        acc[6] += xv * w1v.z; acc[7] += xv * w1v.w;
    }
    #pragma unroll
    for (int e = 0; e < NE; e++) {
        #pragma unroll
        for (int o = 16; o; o >>= 1)
            acc[e] += __shfl_xor_sync(0xffffffffu, acc[e], o);
    }
    if (lane == 0) {
        float lg[NE];
        float m = -1e30f;
        #pragma unroll
        for (int e = 0; e < NE; e++) { lg[e] = acc[e] + rb[e]; m = fmaxf(m, lg[e]); }
        float g[NE], s = 0.f;
        #pragma unroll
        for (int e = 0; e < NE; e++) { g[e] = __expf(lg[e] - m); s += g[e]; }
        float inv = 1.f / s;
        int   bi = 0;
        float bg = -1.f;
        #pragma unroll
        for (int e = 0; e < NE; e++) {
            g[e] *= inv;
            g_gates[(size_t)warp * NE + e] = g[e];
            if (g[e] > bg) { bg = g[e]; bi = e; }  // strict > => first-max, matches argmax
        }
        g_topidx[warp] = bi;
        g_topval[warp] = bg;
    }
}

// ---------------- scan: single block, shuffle-based per-expert prefix -------
// Token order: thread tid owns tokens [tid*8, tid*8+8); lanes/warps ascending
// => first-come order preserved. Only 2 __syncthreads total.
__global__ __launch_bounds__(1024) void scan_kernel(float* __restrict__ out, int y_elems)
{
    __shared__ int   swarp[32][NE];   // per-warp inclusive totals
    __shared__ int   swoff[32][NE];   // per-warp exclusive offsets
    __shared__ float simp [32][NE];   // per-warp importance sums

    int tid  = threadIdx.x;
    int lane = tid & 31;
    int wid  = tid >> 5;
    int base = tid * 8;

    int cnt[NE];
    int eloc[8];
    #pragma unroll
    for (int e = 0; e < NE; e++) cnt[e] = 0;
    #pragma unroll
    for (int j = 0; j < 8; j++) {
        int e = g_topidx[base + j];
        eloc[j] = e;
        cnt[e]++;
    }

    float imp[NE];
    #pragma unroll
    for (int e = 0; e < NE; e++) imp[e] = 0.f;
    #pragma unroll
    for (int j = 0; j < 8; j++) {
        const float* gp = &g_gates[(size_t)(base + j) * NE];
        #pragma unroll
        for (int e = 0; e < NE; e++) imp[e] += gp[e];
    }

    // warp-level: inclusive scan of cnt over lanes; xor-reduce of imp
    int inc[NE];
    #pragma unroll
    for (int e = 0; e < NE; e++) {
        inc[e] = cnt[e];
        #pragma unroll
        for (int o = 1; o < 32; o <<= 1) {
            int v = __shfl_up_sync(0xffffffffu, inc[e], o);
            if (lane >= o) inc[e] += v;
        }
        #pragma unroll
        for (int o = 16; o; o >>= 1)
            imp[e] += __shfl_xor_sync(0xffffffffu, imp[e], o);
    }
    if (lane == 31) {
        #pragma unroll
        for (int e = 0; e < NE; e++) swarp[wid][e] = inc[e];
    }
    if (lane == 0) {
        #pragma unroll
        for (int e = 0; e < NE; e++) simp[wid][e] = imp[e];
    }
    __syncthreads();

    // warp 0: scan the 32 warp totals, reduce importance, emit aux/used
    if (wid == 0) {
        float aux = 0.f;
        #pragma unroll
        for (int e = 0; e < NE; e++) {
            int t = swarp[lane][e];
            int v = t;
            #pragma unroll
            for (int o = 1; o < 32; o <<= 1) {
                int u = __shfl_up_sync(0xffffffffu, v, o);
                if (lane >= o) v += u;
            }
            swoff[lane][e] = v - t;                       // exclusive warp offset
            int tot = __shfl_sync(0xffffffffu, v, 31);    // grand total

            float fi = simp[lane][e];
            #pragma unroll
            for (int o = 16; o; o >>= 1)
                fi += __shfl_xor_sync(0xffffffffu, fi, o);

            if (lane == 0) {
                float load       = (float)tot / (float)T_TOKENS;
                float importance = fi / (float)T_TOKENS;
                aux += importance * load;
                int u = tot < CAP ? tot : CAP;
                g_used[e] = u;
                out[y_elems + 1 + e] = (float)u;
            }
        }
        if (lane == 0) out[y_elems] = aux * (float)NE * 0.01f;
    }
    __syncthreads();

    // per-token ranks
    int c2[NE];
    #pragma unroll
    for (int e = 0; e < NE; e++) c2[e] = swoff[wid][e] + inc[e] - cnt[e];
    #pragma unroll
    for (int j = 0; j < 8; j++) {
        int e = eloc[j];
        g_rank[base + j] = c2[e];
        c2[e]++;
    }
}

// ---------------- dispatch: block per token, write fp16 ----------------
__global__ __launch_bounds__(256) void dispatch_kernel(const float* __restrict__ x)
{
    int t = blockIdx.x;
    int r = g_rank[t];
    if (r >= CAP) return;
    int e = g_topidx[t];
    float4 v = ((const float4*)(x + (size_t)t * DM))[threadIdx.x];
    size_t base = ((size_t)e * CAP + r) * (DM / 4) + threadIdx.x;
    ((uint2*)g_buf)[base] = make_uint2(
        packh2(__float2half(v.x), __float2half(v.y)),
        packh2(__float2half(v.z), __float2half(v.w)));
}

// ---------------- weight fp32 -> fp16 converts (device globals referenced
// from device code — passing __device__ symbols as host args is invalid) ----
__global__ __launch_bounds__(256) void convert_w1(const float* __restrict__ w)
{
    size_t n4 = (size_t)NE * DM * DH / 4;
    for (size_t i = (size_t)blockIdx.x * blockDim.x + threadIdx.x; i < n4;
         i += (size_t)gridDim.x * blockDim.x) {
        float4 a = ((const float4*)w)[i];
        ((uint2*)g_w1)[i] = make_uint2(packh2(__float2half(a.x), __float2half(a.y)),
                                       packh2(__float2half(a.z), __float2half(a.w)));
    }
}
__global__ __launch_bounds__(256) void convert_w2(const float* __restrict__ w)
{
    size_t n4 = (size_t)NE * DM * DH / 4;
    for (size_t i = (size_t)blockIdx.x * blockDim.x + threadIdx.x; i < n4;
         i += (size_t)gridDim.x * blockDim.x) {
        float4 a = ((const float4*)w)[i];
        ((uint2*)g_w2)[i] = make_uint2(packh2(__float2half(a.x), __float2half(a.y)),
                                       packh2(__float2half(a.z), __float2half(a.w)));
    }
}

// ---------------- mma.sync grouped GEMM (pure fp16) ----------------
// Block tile 128(m) x 256(n), 256 threads, 8 warps (2x4), warp tile 64x64,
// k-staged 64, 4-stage cp.async pipeline, register-double-buffered fragments.
#define A_PAD 144
#define B_PAD 528
#define OFF_B 18432
#define STAGE_STRIDE 52224
#define NSTAGE 4
#define FFN_SMEM (NSTAGE * STAGE_STRIDE)

template<int K, int NFULL>
__device__ __forceinline__ void load_stage(
    unsigned sbase, const __half* A, const __half* B, int k0, int col0, int tid)
{
    #pragma unroll
    for (int l = 0; l < 4; l++) {   // A: 1024 chunks (128 rows x 8)
        int i   = tid + l * 256;
        int row = i >> 3, c = i & 7;
        cp16(sbase + row * A_PAD + c * 16, A + (size_t)row * K + k0 + c * 8);
    }
    #pragma unroll
    for (int l = 0; l < 8; l++) {   // B: 2048 chunks (64 k-rows x 32)
        int i  = tid + l * 256;
        int kr = i >> 5, c = i & 31;
        cp16(sbase + OFF_B + kr * B_PAD + c * 16,
             B + (size_t)(k0 + kr) * NFULL + col0 + c * 8);
    }
    CP_COMMIT();
}

template<int K, int NFULL, bool RELU, bool FIRST, int KSPLIT>
__global__ __launch_bounds__(256, 1) void ffn_mma(const float* __restrict__ bias_g)
{
    constexpr int KPER = K / KSPLIT;
    constexpr int S = KPER / 64;

    extern __shared__ __align__(128) char smem[];
    const int e     = blockIdx.z / KSPLIT;
    const int split = blockIdx.z % KSPLIT;
    const int row0  = blockIdx.y * 128;
    if (row0 >= g_used[e]) return;
    const int col0 = blockIdx.x * 256;

    const __half* A = (FIRST ? g_buf : g_h)
                      + ((size_t)e * CAP + row0) * K + (size_t)split * KPER;
    const __half* B = (FIRST ? g_w1 : g_w2)
                      + (size_t)e * K * NFULL + (size_t)split * KPER * NFULL;

    unsigned sb  = smem_u32(smem);
    int tid  = threadIdx.x;
    int lane = tid & 31;
    int wid  = tid >> 5;
    int wm = (wid & 1) * 64;    // 2 warps along m
    int wn = (wid >> 1) * 64;   // 4 warps along n

    float acc[4][8][4];
    #pragma unroll
    for (int t = 0; t < 4; t++)
        #pragma unroll
        for (int n = 0; n < 8; n++)
            #pragma unroll
            for (int j = 0; j < 4; j++) acc[t][n][j] = 0.f;

    // ldmatrix lane address components
    unsigned a_row  = wm + (lane & 15);
    unsigned a_koff = (lane >> 4) * 16;     // byte offset (k half of 16-k chunk)
    unsigned b_krow = lane & 15;
    unsigned b_ncol = wn + ((lane & 16) ? 8 : 0);

    // double-buffered fragments
    unsigned ah[2][4][4], bh[2][8][2];

    auto ldfrag = [&](unsigned ab, int kk, int buf) {
        #pragma unroll
        for (int t = 0; t < 4; t++)
            ldsm4(ah[buf][t], ab + (a_row + t * 16) * A_PAD + kk * 32 + a_koff);
        #pragma unroll
        for (int h = 0; h < 4; h++) {
            unsigned r[4];
            ldsm4t(r, ab + OFF_B + (kk * 16 + b_krow) * B_PAD + (b_ncol + h * 16) * 2);
            bh[buf][h * 2][0] = r[0]; bh[buf][h * 2][1] = r[1];
            bh[buf][h * 2 + 1][0] = r[2]; bh[buf][h * 2 + 1][1] = r[3];
        }
    };

    // prologue: stages 0,1,2 in flight
    load_stage<K, NFULL>(sb, A, B, 0, col0, tid);
    load_stage<K, NFULL>(sb + STAGE_STRIDE, A, B, 64, col0, tid);
    load_stage<K, NFULL>(sb + 2 * STAGE_STRIDE, A, B, 128, col0, tid);

    #pragma unroll 1
    for (int s = 0; s < S; s++) {
        CP_WAIT(2);
        __syncthreads();
        if (s + 3 < S)
            load_stage<K, NFULL>(sb + ((s + 3) % NSTAGE) * STAGE_STRIDE, A, B,
                                 (s + 3) * 64, col0, tid);
        else
            CP_COMMIT();     // empty group keeps wait accounting uniform

        unsigned ab = sb + (s % NSTAGE) * STAGE_STRIDE;
        ldfrag(ab, 0, 0);
        #pragma unroll
        for (int kk = 0; kk < 4; kk++) {
            int cur = kk & 1;
            if (kk < 3) ldfrag(ab, kk + 1, cur ^ 1);
            #pragma unroll
            for (int t = 0; t < 4; t++)
                #pragma unroll
                for (int n = 0; n < 8; n++)
                    mma_f16(acc[t][n], ah[cur][t], bh[cur][n]);
        }
    }

    // epilogue
    int r0l   = lane >> 2;
    int cpair = (lane & 3) * 2;
    if (FIRST) {
        const float* bias = bias_g + (size_t)e * NFULL + col0;
        #pragma unroll
        for (int t = 0; t < 4; t++) {
            #pragma unroll
            for (int n = 0; n < 8; n++) {
                int col = wn + n * 8 + cpair;
                float b0 = __ldg(bias + col), b1 = __ldg(bias + col + 1);
                int rowA = row0 + wm + t * 16 + r0l;
                #pragma unroll
                for (int half = 0; half < 2; half++) {
                    int rg = rowA + half * 8;
                    float v0 = fmaxf(acc[t][n][half * 2]     + b0, 0.f);
                    float v1 = fmaxf(acc[t][n][half * 2 + 1] + b1, 0.f);
                    size_t idx = ((size_t)e * CAP + rg) * NFULL + col0 + col;
                    ((unsigned*)g_h)[idx >> 1] = packh2(__float2half(v0), __float2half(v1));
                }
            }
        }
    } else {
        float* part = g_part + (size_t)split * NE * (size_t)CAP * DM;
        #pragma unroll
        for (int t = 0; t < 4; t++) {
            #pragma unroll
            for (int n = 0; n < 8; n++) {
                int col = wn + n * 8 + cpair;
                int rowA = row0 + wm + t * 16 + r0l;
                #pragma unroll
                for (int half = 0; half < 2; half++) {
                    int rg = rowA + half * 8;
                    size_t idx = ((size_t)e * CAP + rg) * NFULL + col0 + col;
                    *(float2*)(part + idx) =
                        make_float2(acc[t][n][half * 2], acc[t][n][half * 2 + 1]);
                }
            }
        }
    }
}

// ---------------- combine: sum split-K partials + bias, scale by gate ------
__global__ __launch_bounds__(256) void combine_kernel(
    float* __restrict__ out, const float* __restrict__ b2)
{
    int t = blockIdx.x;
    int r = g_rank[t];
    float4* dst = (float4*)(out + (size_t)t * DM);
    if (r < CAP) {
        int   e = g_topidx[t];
        float v = g_topval[t];
        size_t idx = ((size_t)e * CAP + r) * (DM / 4) + threadIdx.x;
        float4 p0 = ((const float4*)g_part)[idx];
        float4 p1 = ((const float4*)g_part)[idx + (size_t)NE * CAP * DM / 4];
        float4 b  = ((const float4*)(b2 + (size_t)e * DM))[threadIdx.x];
        float4 s;
        s.x = (p0.x + p1.x + b.x) * v;
        s.y = (p0.y + p1.y + b.y) * v;
        s.z = (p0.z + p1.z + b.z) * v;
        s.w = (p0.w + p1.w + b.w) * v;
        dst[threadIdx.x] = s;
    } else {
        dst[threadIdx.x] = make_float4(0.f, 0.f, 0.f, 0.f);
    }
}

extern "C" void kernel_launch(void* const* d_in, const int* in_sizes, int n_in,
                              void* d_out, int out_size)
{
    const float* x  = (const float*)d_in[0];
    const float* rw = (const float*)d_in[1];
    const float* rb = (const float*)d_in[2];
    const float* w1 = (const float*)d_in[3];
    const float* b1 = (const float*)d_in[4];
    const float* w2 = (const float*)d_in[5];
    const float* b2 = (const float*)d_in[6];
    float* out = (float*)d_out;

    int y_elems = in_sizes[0];

    cudaFuncSetAttribute(ffn_mma<DM, DH, true,  true,  1>,
                         cudaFuncAttributeMaxDynamicSharedMemorySize, FFN_SMEM);
    cudaFuncSetAttribute(ffn_mma<DH, DM, false, false, 2>,
                         cudaFuncAttributeMaxDynamicSharedMemorySize, FFN_SMEM);

    // Two side branches: W1 convert (needed by GEMM1), W2 convert (needed only
    // by GEMM2 -> overlaps the router chain AND all of GEMM1's compute-bound run).
    cudaStream_t s2, s3;
    cudaStreamCreateWithFlags(&s2, cudaStreamNonBlocking);
    cudaStreamCreateWithFlags(&s3, cudaStreamNonBlocking);
    cudaEvent_t evFork, ev1, ev2;
    cudaEventCreateWithFlags(&evFork, cudaEventDisableTiming);
    cudaEventCreateWithFlags(&ev1, cudaEventDisableTiming);
    cudaEventCreateWithFlags(&ev2, cudaEventDisableTiming);

    cudaEventRecord(evFork, 0);
    cudaStreamWaitEvent(s2, evFork, 0);
    cudaStreamWaitEvent(s3, evFork, 0);
    convert_w1<<<2048, 256, 0, s2>>>(w1);
    cudaEventRecord(ev1, s2);
    convert_w2<<<2048, 256, 0, s3>>>(w2);
    cudaEventRecord(ev2, s3);

    // Main chain, concurrent with the converts.
    router_kernel<<<T_TOKENS / 8, 256>>>(x, rw, rb);
    scan_kernel<<<1, 1024>>>(out, y_elems);
    dispatch_kernel<<<T_TOKENS, 256>>>(x);

    cudaStreamWaitEvent(0, ev1, 0);   // GEMM1 needs W1
    ffn_mma<DM, DH, true,  true,  1><<<dim3(DH / 256, CAP / 128, NE),     256, FFN_SMEM>>>(b1);

    cudaStreamWaitEvent(0, ev2, 0);   // GEMM2 needs W2
    ffn_mma<DH, DM, false, false, 2><<<dim3(DM / 256, CAP / 128, NE * 2), 256, FFN_SMEM>>>(b2);

    combine_kernel<<<T_TOKENS, 256>>>(out, b2);

    cudaEventDestroy(evFork);
    cudaEventDestroy(ev1);
    cudaEventDestroy(ev2);
    cudaStreamDestroy(s2);
    cudaStreamDestroy(s3);
}